// round 1
// baseline (speedup 1.0000x reference)
#include <cuda_runtime.h>

#define NT 256
#define L_IN 4096
#define L1V 2047
#define L2V 1023
#define L3V 1021
#define DZV 30
#define CV 10
#define NPG 15          // nets per CTA group (2 groups)
#define B_TOT 512

__constant__ float cW1[DZV*96];   // [d][oc<4][ch<8][k<3]
__constant__ float cB1[DZV*4];
__constant__ float cW2[DZV*96];   // [d][oc<8][ch<4][k<3]
__constant__ float cB2[DZV*8];
__constant__ float cW3[DZV*192];  // [d][oc<8][ch<8][k<3]
__constant__ float cB3[DZV*8];
__constant__ float cWh[DZV*80];   // [d][c<10][j<8]
__constant__ float cBh[DZV*10];
__constant__ float cZ[DZV];

#define H1_STR 2048
#define H2_STR 1024
#define H1_OFF (8*L_IN)
#define H2_OFF (H1_OFF + 4*H1_STR)
#define RED_OFF (H2_OFF + 8*H2_STR)
#define SMEM_FLOATS (RED_OFF + 80)

__global__ void zero_out_kernel(float* out, int n) {
    int i = blockIdx.x * blockDim.x + threadIdx.x;
    if (i < n) out[i] = 0.0f;
}

__global__ __launch_bounds__(NT, 1)
void ensemble_kernel(const int* __restrict__ ids,
                     const float* __restrict__ mask,
                     const float* __restrict__ embed,
                     float* __restrict__ out)
{
    extern __shared__ float sm[];
    float* xs  = sm;               // [8][4096]
    float* h1  = sm + H1_OFF;      // [4][2048]
    float* h2  = sm + H2_OFF;      // [8][1024]
    float* red = sm + RED_OFF;     // [8 warps][8]

    const int tid  = threadIdx.x;
    const int lane = tid & 31;
    const int warp = tid >> 5;
    const int b    = blockIdx.x;
    const int g    = blockIdx.y;

    // ---- gather embeddings (masked) into smem, channel-major ----
    #pragma unroll 1
    for (int i = tid; i < L_IN; i += NT) {
        int   id = __ldg(&ids[b*L_IN + i]);
        float m  = __ldg(&mask[b*L_IN + i]);
        float4 e0 = __ldg((const float4*)(embed + (size_t)id*8));
        float4 e1 = __ldg((const float4*)(embed + (size_t)id*8 + 4));
        xs[0*L_IN+i] = e0.x*m; xs[1*L_IN+i] = e0.y*m;
        xs[2*L_IN+i] = e0.z*m; xs[3*L_IN+i] = e0.w*m;
        xs[4*L_IN+i] = e1.x*m; xs[5*L_IN+i] = e1.y*m;
        xs[6*L_IN+i] = e1.z*m; xs[7*L_IN+i] = e1.w*m;
    }
    __syncthreads();

    float oacc[CV];
    #pragma unroll
    for (int c = 0; c < CV; c++) oacc[c] = 0.0f;

    #pragma unroll 1
    for (int dn = 0; dn < NPG; dn++) {
        const int d = g*NPG + dn;

        // ======== conv1: xs[8][4096] -> h1[4][2047], K3 S2 + ReLU ========
        {
            float w[96];
            #pragma unroll
            for (int i = 0; i < 96; i++) w[i] = cW1[d*96 + i];
            float bb[4];
            #pragma unroll
            for (int i = 0; i < 4; i++) bb[i] = cB1[d*4 + i];

            #pragma unroll 1
            for (int it = 0; it < 2; it++) {
                const int p0 = it*(NT*4) + tid*4;
                const int ib = 2*p0;
                float acc[4][4];
                #pragma unroll
                for (int pos = 0; pos < 4; pos++)
                    #pragma unroll
                    for (int oc = 0; oc < 4; oc++) acc[pos][oc] = bb[oc];

                #pragma unroll
                for (int ch = 0; ch < 8; ch++) {
                    const float* row = xs + ch*L_IN + ib;
                    float4 v0 = *(const float4*)row;
                    float4 v1 = *(const float4*)(row + 4);
                    float  w8 = (ib + 8 < L_IN) ? row[8] : 0.0f;
                    float win[9] = {v0.x,v0.y,v0.z,v0.w, v1.x,v1.y,v1.z,v1.w, w8};
                    #pragma unroll
                    for (int pos = 0; pos < 4; pos++) {
                        #pragma unroll
                        for (int k = 0; k < 3; k++) {
                            const float xv = win[2*pos + k];
                            #pragma unroll
                            for (int oc = 0; oc < 4; oc++)
                                acc[pos][oc] = fmaf(w[(oc*8+ch)*3+k], xv, acc[pos][oc]);
                        }
                    }
                }
                if (p0 + 3 < L1V) {
                    #pragma unroll
                    for (int oc = 0; oc < 4; oc++) {
                        float4 st = make_float4(fmaxf(acc[0][oc],0.f), fmaxf(acc[1][oc],0.f),
                                                fmaxf(acc[2][oc],0.f), fmaxf(acc[3][oc],0.f));
                        *(float4*)(h1 + oc*H1_STR + p0) = st;
                    }
                } else {
                    #pragma unroll
                    for (int pos = 0; pos < 4; pos++) {
                        if (p0 + pos < L1V) {
                            #pragma unroll
                            for (int oc = 0; oc < 4; oc++)
                                h1[oc*H1_STR + p0 + pos] = fmaxf(acc[pos][oc], 0.f);
                        }
                    }
                }
            }
        }
        __syncthreads();

        // ======== conv2: h1[4][2047] -> h2[8][1023], K3 S2 + ReLU ========
        {
            float w[96];
            #pragma unroll
            for (int i = 0; i < 96; i++) w[i] = cW2[d*96 + i];
            float bb[8];
            #pragma unroll
            for (int i = 0; i < 8; i++) bb[i] = cB2[d*8 + i];

            #pragma unroll 1
            for (int it = 0; it < 2; it++) {
                const int p0 = it*(NT*2) + tid*2;
                const int ib = 2*p0;
                float acc[2][8];
                #pragma unroll
                for (int pos = 0; pos < 2; pos++)
                    #pragma unroll
                    for (int oc = 0; oc < 8; oc++) acc[pos][oc] = bb[oc];

                #pragma unroll
                for (int ch = 0; ch < 4; ch++) {
                    const float* row = h1 + ch*H1_STR + ib;
                    float4 v0 = *(const float4*)row;
                    float  w4 = (ib + 4 < L1V) ? row[4] : 0.0f;
                    float win[5] = {v0.x,v0.y,v0.z,v0.w, w4};
                    #pragma unroll
                    for (int pos = 0; pos < 2; pos++) {
                        #pragma unroll
                        for (int k = 0; k < 3; k++) {
                            const float xv = win[2*pos + k];
                            #pragma unroll
                            for (int oc = 0; oc < 8; oc++)
                                acc[pos][oc] = fmaf(w[(oc*4+ch)*3+k], xv, acc[pos][oc]);
                        }
                    }
                }
                if (p0 + 1 < L2V) {
                    #pragma unroll
                    for (int oc = 0; oc < 8; oc++) {
                        float2 st = make_float2(fmaxf(acc[0][oc],0.f), fmaxf(acc[1][oc],0.f));
                        *(float2*)(h2 + oc*H2_STR + p0) = st;
                    }
                } else if (p0 < L2V) {
                    #pragma unroll
                    for (int oc = 0; oc < 8; oc++)
                        h2[oc*H2_STR + p0] = fmaxf(acc[0][oc], 0.f);
                }
            }
        }
        __syncthreads();

        // ======== conv3 + ReLU + mean pool: h2[8][1023] -> psum[8] ========
        float psum[8];
        #pragma unroll
        for (int i = 0; i < 8; i++) psum[i] = 0.f;
        {
            const int p0 = tid*4;
            #pragma unroll
            for (int half = 0; half < 2; half++) {
                float w[96];
                #pragma unroll
                for (int i = 0; i < 96; i++) w[i] = cW3[d*192 + half*96 + i];
                float bb[4];
                #pragma unroll
                for (int i = 0; i < 4; i++) bb[i] = cB3[d*8 + half*4 + i];

                float acc[4][4];
                #pragma unroll
                for (int pos = 0; pos < 4; pos++)
                    #pragma unroll
                    for (int oc = 0; oc < 4; oc++) acc[pos][oc] = bb[oc];

                #pragma unroll
                for (int ch = 0; ch < 8; ch++) {
                    const float* row = h2 + ch*H2_STR + p0;
                    float4 v0 = *(const float4*)row;
                    float  a4 = (p0 + 4 < L2V) ? row[4] : 0.0f;
                    float  a5 = (p0 + 5 < L2V) ? row[5] : 0.0f;
                    float win[6] = {v0.x,v0.y,v0.z,v0.w, a4, a5};
                    #pragma unroll
                    for (int pos = 0; pos < 4; pos++) {
                        #pragma unroll
                        for (int k = 0; k < 3; k++) {
                            const float xv = win[pos + k];
                            #pragma unroll
                            for (int oc = 0; oc < 4; oc++)
                                acc[pos][oc] = fmaf(w[(oc*8+ch)*3+k], xv, acc[pos][oc]);
                        }
                    }
                }
                #pragma unroll
                for (int pos = 0; pos < 4; pos++) {
                    if (p0 + pos < L3V) {
                        #pragma unroll
                        for (int oc = 0; oc < 4; oc++)
                            psum[half*4 + oc] += fmaxf(acc[pos][oc], 0.f);
                    }
                }
            }
        }

        // ---- block reduction of pooled sums ----
        #pragma unroll
        for (int oc = 0; oc < 8; oc++) {
            float s = psum[oc];
            #pragma unroll
            for (int off = 16; off > 0; off >>= 1)
                s += __shfl_down_sync(0xFFFFFFFFu, s, off);
            if (lane == 0) red[warp*8 + oc] = s;
        }
        __syncthreads();

        if (tid == 0) {
            float pooled[8];
            #pragma unroll
            for (int oc = 0; oc < 8; oc++) {
                float s = 0.f;
                #pragma unroll
                for (int wv = 0; wv < 8; wv++) s += red[wv*8 + oc];
                pooled[oc] = s * (1.0f/1021.0f);
            }
            const float zd = cZ[d];
            #pragma unroll
            for (int c = 0; c < CV; c++) {
                float v = cBh[d*10 + c];
                #pragma unroll
                for (int j = 0; j < 8; j++)
                    v = fmaf(pooled[j], cWh[(d*10+c)*8 + j], v);
                oacc[c] = fmaf(zd, v, oacc[c]);
            }
        }
        // no extra barrier needed: red is rewritten only after two more
        // __syncthreads (conv1-end, conv2-end) that thread 0 must also pass.
    }

    if (tid == 0) {
        #pragma unroll
        for (int c = 0; c < CV; c++)
            atomicAdd(&out[b*CV + c], oacc[c]);
    }
}

extern "C" void kernel_launch(void* const* d_in, const int* in_sizes, int n_in,
                              void* d_out, int out_size) {
    const int*   ids  = (const int*)  d_in[0];
    const float* mask = (const float*)d_in[1];
    const float* z    = (const float*)d_in[2];
    const float* emb  = (const float*)d_in[3];
    const float* W1   = (const float*)d_in[4];
    const float* b1   = (const float*)d_in[5];
    const float* W2   = (const float*)d_in[6];
    const float* b2   = (const float*)d_in[7];
    const float* W3   = (const float*)d_in[8];
    const float* b3   = (const float*)d_in[9];
    const float* Wh   = (const float*)d_in[10];
    const float* bh   = (const float*)d_in[11];
    float* out = (float*)d_out;

    cudaMemcpyToSymbolAsync(cW1, W1, DZV*96*sizeof(float),  0, cudaMemcpyDeviceToDevice, 0);
    cudaMemcpyToSymbolAsync(cB1, b1, DZV*4*sizeof(float),   0, cudaMemcpyDeviceToDevice, 0);
    cudaMemcpyToSymbolAsync(cW2, W2, DZV*96*sizeof(float),  0, cudaMemcpyDeviceToDevice, 0);
    cudaMemcpyToSymbolAsync(cB2, b2, DZV*8*sizeof(float),   0, cudaMemcpyDeviceToDevice, 0);
    cudaMemcpyToSymbolAsync(cW3, W3, DZV*192*sizeof(float), 0, cudaMemcpyDeviceToDevice, 0);
    cudaMemcpyToSymbolAsync(cB3, b3, DZV*8*sizeof(float),   0, cudaMemcpyDeviceToDevice, 0);
    cudaMemcpyToSymbolAsync(cWh, Wh, DZV*80*sizeof(float),  0, cudaMemcpyDeviceToDevice, 0);
    cudaMemcpyToSymbolAsync(cBh, bh, DZV*10*sizeof(float),  0, cudaMemcpyDeviceToDevice, 0);
    cudaMemcpyToSymbolAsync(cZ,  z,  DZV*sizeof(float),     0, cudaMemcpyDeviceToDevice, 0);

    cudaFuncSetAttribute(ensemble_kernel,
                         cudaFuncAttributeMaxDynamicSharedMemorySize,
                         SMEM_FLOATS * (int)sizeof(float));

    zero_out_kernel<<<(B_TOT*CV + 255)/256, 256>>>(out, B_TOT*CV);
    ensemble_kernel<<<dim3(B_TOT, 2), NT, SMEM_FLOATS * (int)sizeof(float)>>>(ids, mask, emb, out);
}